// round 1
// baseline (speedup 1.0000x reference)
#include <cuda_runtime.h>
#include <cuda_bf16.h>

// ---------------------------------------------------------------------------
// QGCN forward on GB300.
//   x1  = scatter(x@W1) + b1
//   h   = x1 + relu(x1)
//   h2  = scatter(h@W2) + b2
//   h   = x1 + relu(h2)
//   out = scatter(h@W3) + b3
// scatter = segment_sum over edges with edge weights (gather src, red-add dst).
// ---------------------------------------------------------------------------

#define N_NODES 50000
#define N_EDGES 800000

// Scratch buffers (no cudaMalloc allowed).
__device__ float g_bufA[N_NODES * 128];
__device__ float g_bufB[N_NODES * 128];
__device__ float g_bufC[N_NODES * 128];

// ---------------------------------------------------------------------------
// GEMM: Y[N, DOUT] = X[N, 128] @ W[128, DOUT]
// Block: 256 threads, 64 rows. W fully staged in SMEM, X tile staged in SMEM.
// Thread tile: RPT rows x 8 cols.
// ---------------------------------------------------------------------------
template <int DOUT>
__global__ __launch_bounds__(256, 2) void gemm_kernel(
    const float* __restrict__ X, const float* __restrict__ W,
    float* __restrict__ Y, int N)
{
    extern __shared__ float smem[];
    float* ws = smem;                 // 128 * DOUT
    float* xs = smem + 128 * DOUT;    // 64 rows * 132 (padded)
    const int XS = 132;

    int row0 = blockIdx.x * 64;

    // Stage W (row-major [128, DOUT])
    for (int i = threadIdx.x; i < 128 * DOUT / 4; i += 256)
        ((float4*)ws)[i] = ((const float4*)W)[i];

    // Stage X tile (64 rows x 128), zero-pad past N
    for (int i = threadIdx.x; i < 64 * 32; i += 256) {
        int r = i >> 5, c = i & 31;
        int gr = row0 + r;
        float4 v = make_float4(0.f, 0.f, 0.f, 0.f);
        if (gr < N) v = ((const float4*)X)[gr * 32 + c];
        *(float4*)&xs[r * XS + c * 4] = v;
    }
    __syncthreads();

    constexpr int CG  = DOUT / 8;   // col-groups: 16 (D=128) or 8 (D=64)
    constexpr int RPT = CG / 4;     // rows per thread: 4 or 2
    int cg   = threadIdx.x % CG;
    int rg   = threadIdx.x / CG;
    int col0 = cg * 8;
    int r0   = rg * RPT;

    float acc[RPT][8];
#pragma unroll
    for (int r = 0; r < RPT; r++)
#pragma unroll
        for (int c = 0; c < 8; c++) acc[r][c] = 0.f;

#pragma unroll 4
    for (int k = 0; k < 128; k++) {
        float4 w0 = *(const float4*)&ws[k * DOUT + col0];
        float4 w1 = *(const float4*)&ws[k * DOUT + col0 + 4];
#pragma unroll
        for (int r = 0; r < RPT; r++) {
            float a = xs[(r0 + r) * XS + k];
            acc[r][0] = fmaf(a, w0.x, acc[r][0]);
            acc[r][1] = fmaf(a, w0.y, acc[r][1]);
            acc[r][2] = fmaf(a, w0.z, acc[r][2]);
            acc[r][3] = fmaf(a, w0.w, acc[r][3]);
            acc[r][4] = fmaf(a, w1.x, acc[r][4]);
            acc[r][5] = fmaf(a, w1.y, acc[r][5]);
            acc[r][6] = fmaf(a, w1.z, acc[r][6]);
            acc[r][7] = fmaf(a, w1.w, acc[r][7]);
        }
    }

#pragma unroll
    for (int r = 0; r < RPT; r++) {
        int gr = row0 + r0 + r;
        if (gr < N) {
            float4 o0 = make_float4(acc[r][0], acc[r][1], acc[r][2], acc[r][3]);
            float4 o1 = make_float4(acc[r][4], acc[r][5], acc[r][6], acc[r][7]);
            ((float4*)Y)[(gr * DOUT + col0) >> 2]       = o0;
            ((float4*)Y)[((gr * DOUT + col0) >> 2) + 1] = o1;
        }
    }
}

// ---------------------------------------------------------------------------
// Edge scatter: out[dst[e]] += H[src[e]] * ew[e]   (vector red.add.v4.f32)
// One thread per (edge, float4-chunk). SH = log2(D/4): 5 for D=128, 4 for D=64.
// ---------------------------------------------------------------------------
template <int SH>
__global__ __launch_bounds__(256) void scatter_kernel(
    const float* __restrict__ H, const int* __restrict__ src,
    const int* __restrict__ dst, const float* __restrict__ ew,
    float* __restrict__ out, int E)
{
    int idx = blockIdx.x * blockDim.x + threadIdx.x;
    int e = idx >> SH;
    if (e >= E) return;
    int c = idx & ((1 << SH) - 1);

    int s  = __ldg(&src[e]);
    int d  = __ldg(&dst[e]);
    float w = __ldg(&ew[e]);

    float4 v = ((const float4*)H)[(s << SH) + c];
    float4* p = ((float4*)out) + ((d << SH) + c);
    asm volatile("red.global.add.v4.f32 [%0], {%1, %2, %3, %4};"
                 :: "l"(p), "f"(v.x * w), "f"(v.y * w), "f"(v.z * w), "f"(v.w * w)
                 : "memory");
}

// ---------------------------------------------------------------------------
// out[i] = b[i & mask]   (bias broadcast init; scatter then accumulates on top)
// ---------------------------------------------------------------------------
__global__ __launch_bounds__(256) void init_bias_kernel(
    float* __restrict__ out, const float* __restrict__ b, int total, int mask)
{
    int i = blockIdx.x * blockDim.x + threadIdx.x;
    if (i < total) out[i] = __ldg(&b[i & mask]);
}

// C = B + relu(B)
__global__ __launch_bounds__(256) void resid_a_kernel(
    float* __restrict__ C, const float* __restrict__ B, int total4)
{
    int i = blockIdx.x * blockDim.x + threadIdx.x;
    if (i >= total4) return;
    float4 v = ((const float4*)B)[i];
    float4 o;
    o.x = v.x + fmaxf(v.x, 0.f);
    o.y = v.y + fmaxf(v.y, 0.f);
    o.z = v.z + fmaxf(v.z, 0.f);
    o.w = v.w + fmaxf(v.w, 0.f);
    ((float4*)C)[i] = o;
}

// C = B + relu(C)   (in-place on C)
__global__ __launch_bounds__(256) void resid_b_kernel(
    float* __restrict__ C, const float* __restrict__ B, int total4)
{
    int i = blockIdx.x * blockDim.x + threadIdx.x;
    if (i >= total4) return;
    float4 v = ((const float4*)C)[i];
    float4 b = ((const float4*)B)[i];
    float4 o;
    o.x = b.x + fmaxf(v.x, 0.f);
    o.y = b.y + fmaxf(v.y, 0.f);
    o.z = b.z + fmaxf(v.z, 0.f);
    o.w = b.w + fmaxf(v.w, 0.f);
    ((float4*)C)[i] = o;
}

// ---------------------------------------------------------------------------

extern "C" void kernel_launch(void* const* d_in, const int* in_sizes, int n_in,
                              void* d_out, int out_size)
{
    const float* x  = (const float*)d_in[0];
    const int*   ei = (const int*)d_in[1];
    const float* ea = (const float*)d_in[2];
    const float* W1 = (const float*)d_in[3];
    const float* b1 = (const float*)d_in[4];
    const float* W2 = (const float*)d_in[5];
    const float* b2 = (const float*)d_in[6];
    const float* W3 = (const float*)d_in[7];
    const float* b3 = (const float*)d_in[8];
    float* out = (float*)d_out;

    const int N = N_NODES;
    const int E = N_EDGES;
    const int* src = ei;
    const int* dst = ei + E;

    float *A, *B, *C;
    cudaGetSymbolAddress((void**)&A, g_bufA);
    cudaGetSymbolAddress((void**)&B, g_bufB);
    cudaGetSymbolAddress((void**)&C, g_bufC);

    const size_t SMEM128 = (size_t)(128 * 128 + 64 * 132) * 4;  // 99328
    const size_t SMEM64  = (size_t)(128 * 64  + 64 * 132) * 4;  // 66560
    cudaFuncSetAttribute(gemm_kernel<128>, cudaFuncAttributeMaxDynamicSharedMemorySize, (int)SMEM128);
    cudaFuncSetAttribute(gemm_kernel<64>,  cudaFuncAttributeMaxDynamicSharedMemorySize, (int)SMEM64);

    const int gemm_blocks = (N + 63) / 64;
    const int ew_total    = N * 128;               // 6.4M
    const int ew_blocks   = (ew_total + 255) / 256;
    const int r4_total    = ew_total / 4;
    const int r4_blocks   = (r4_total + 255) / 256;
    const int sc128_blk   = (E * 32 + 255) / 256;  // 100000
    const int sc64_blk    = (E * 16 + 255) / 256;  // 50000
    const int out_total   = N * 64;
    const int out_blocks  = (out_total + 255) / 256;

    // --- Layer 0: x1 = scatter(x@W1) + b1 ---
    gemm_kernel<128><<<gemm_blocks, 256, SMEM128>>>(x, W1, A, N);
    init_bias_kernel<<<ew_blocks, 256>>>(B, b1, ew_total, 127);
    scatter_kernel<5><<<sc128_blk, 256>>>(A, src, dst, ea, B, E);   // B = x1
    resid_a_kernel<<<r4_blocks, 256>>>(C, B, r4_total);             // C = x1 + relu(x1)

    // --- Layer 1: h = x1 + relu(scatter(h@W2) + b2) ---
    gemm_kernel<128><<<gemm_blocks, 256, SMEM128>>>(C, W2, A, N);
    init_bias_kernel<<<ew_blocks, 256>>>(C, b2, ew_total, 127);
    scatter_kernel<5><<<sc128_blk, 256>>>(A, src, dst, ea, C, E);   // C = h2
    resid_b_kernel<<<r4_blocks, 256>>>(C, B, r4_total);             // C = x1 + relu(h2)

    // --- Layer 2: out = scatter(h@W3) + b3 ---
    gemm_kernel<64><<<gemm_blocks, 256, SMEM64>>>(C, W3, A, N);
    init_bias_kernel<<<out_blocks, 256>>>(out, b3, out_total, 63);
    scatter_kernel<4><<<sc64_blk, 256>>>(A, src, dst, ea, out, E);
}

// round 2
// speedup vs baseline: 1.2194x; 1.2194x over previous
#include <cuda_runtime.h>
#include <cuda_bf16.h>

// ---------------------------------------------------------------------------
// QGCN forward on GB300 — CSR gather formulation (no fp atomics).
//   CSR build (per call): histogram(dst) -> scan -> place (src, w) by dst.
//   Layer l: GEMM (X@W) -> gather-aggregate per dst node (+bias, fused
//   residual/relu epilogues).
// ---------------------------------------------------------------------------

#define N_NODES 50000
#define N_EDGES 800000

// Scratch (no cudaMalloc allowed).
__device__ float  g_bufA[N_NODES * 128];
__device__ float  g_bufB[N_NODES * 128];
__device__ float  g_bufC[N_NODES * 128];
__device__ int    g_deg[N_NODES];
__device__ int    g_indptr[N_NODES];
__device__ int    g_cursor[N_NODES];
__device__ float2 g_edges[N_EDGES];   // {src (bit-cast int), weight}

// ---------------------------------------------------------------------------
// GEMM: Y[N, DOUT] = X[N, 128] @ W[128, DOUT]
// ---------------------------------------------------------------------------
template <int DOUT>
__global__ __launch_bounds__(256, 2) void gemm_kernel(
    const float* __restrict__ X, const float* __restrict__ W,
    float* __restrict__ Y, int N)
{
    extern __shared__ float smem[];
    float* ws = smem;                 // 128 * DOUT
    float* xs = smem + 128 * DOUT;    // 64 rows * 132 (padded)
    const int XS = 132;

    int row0 = blockIdx.x * 64;

    for (int i = threadIdx.x; i < 128 * DOUT / 4; i += 256)
        ((float4*)ws)[i] = ((const float4*)W)[i];

    for (int i = threadIdx.x; i < 64 * 32; i += 256) {
        int r = i >> 5, c = i & 31;
        int gr = row0 + r;
        float4 v = make_float4(0.f, 0.f, 0.f, 0.f);
        if (gr < N) v = ((const float4*)X)[gr * 32 + c];
        *(float4*)&xs[r * XS + c * 4] = v;
    }
    __syncthreads();

    constexpr int CG  = DOUT / 8;
    constexpr int RPT = CG / 4;
    int cg   = threadIdx.x % CG;
    int rg   = threadIdx.x / CG;
    int col0 = cg * 8;
    int r0   = rg * RPT;

    float acc[RPT][8];
#pragma unroll
    for (int r = 0; r < RPT; r++)
#pragma unroll
        for (int c = 0; c < 8; c++) acc[r][c] = 0.f;

#pragma unroll 4
    for (int k = 0; k < 128; k++) {
        float4 w0 = *(const float4*)&ws[k * DOUT + col0];
        float4 w1 = *(const float4*)&ws[k * DOUT + col0 + 4];
#pragma unroll
        for (int r = 0; r < RPT; r++) {
            float a = xs[(r0 + r) * XS + k];
            acc[r][0] = fmaf(a, w0.x, acc[r][0]);
            acc[r][1] = fmaf(a, w0.y, acc[r][1]);
            acc[r][2] = fmaf(a, w0.z, acc[r][2]);
            acc[r][3] = fmaf(a, w0.w, acc[r][3]);
            acc[r][4] = fmaf(a, w1.x, acc[r][4]);
            acc[r][5] = fmaf(a, w1.y, acc[r][5]);
            acc[r][6] = fmaf(a, w1.z, acc[r][6]);
            acc[r][7] = fmaf(a, w1.w, acc[r][7]);
        }
    }

#pragma unroll
    for (int r = 0; r < RPT; r++) {
        int gr = row0 + r0 + r;
        if (gr < N) {
            float4 o0 = make_float4(acc[r][0], acc[r][1], acc[r][2], acc[r][3]);
            float4 o1 = make_float4(acc[r][4], acc[r][5], acc[r][6], acc[r][7]);
            ((float4*)Y)[(gr * DOUT + col0) >> 2]       = o0;
            ((float4*)Y)[((gr * DOUT + col0) >> 2) + 1] = o1;
        }
    }
}

// ---------------------------------------------------------------------------
// CSR build
// ---------------------------------------------------------------------------
__global__ __launch_bounds__(256) void hist_kernel(
    const int* __restrict__ dst, int* __restrict__ deg, int E)
{
    int e = blockIdx.x * blockDim.x + threadIdx.x;
    if (e < E) atomicAdd(&deg[__ldg(&dst[e])], 1);
}

// Single-block exclusive scan over 50000 degrees.
__global__ __launch_bounds__(1024) void scan_kernel(
    const int* __restrict__ deg, int* __restrict__ indptr,
    int* __restrict__ cursor)
{
    __shared__ int sh[1024];
    const int CHUNK = (N_NODES + 1023) / 1024;   // 49
    int t = threadIdx.x;
    int begin = t * CHUNK;
    int end   = begin + CHUNK; if (end > N_NODES) end = N_NODES;

    int s = 0;
    for (int i = begin; i < end; i++) s += deg[i];
    sh[t] = s;
    __syncthreads();

    // Hillis-Steele inclusive scan
    for (int off = 1; off < 1024; off <<= 1) {
        int v = sh[t];
        int a = (t >= off) ? sh[t - off] : 0;
        __syncthreads();
        sh[t] = v + a;
        __syncthreads();
    }

    int run = (t == 0) ? 0 : sh[t - 1];
    for (int i = begin; i < end; i++) {
        indptr[i] = run;
        cursor[i] = run;
        run += deg[i];
    }
}

__global__ __launch_bounds__(256) void place_kernel(
    const int* __restrict__ src, const int* __restrict__ dst,
    const float* __restrict__ ew, int* __restrict__ cursor,
    float2* __restrict__ edges, int E)
{
    int e = blockIdx.x * blockDim.x + threadIdx.x;
    if (e >= E) return;
    int d = __ldg(&dst[e]);
    int p = atomicAdd(&cursor[d], 1);
    edges[p] = make_float2(__int_as_float(__ldg(&src[e])), __ldg(&ew[e]));
}

// ---------------------------------------------------------------------------
// Gather-aggregate, D=128: one warp per dst node, lane = float4 chunk.
// MODE 0: val=acc+b; out0[n]=val; out1[n]=val+relu(val)         (layer 0)
// MODE 1: val=acc+b; out0[n]=Bres[n]+relu(val)                  (layer 1)
// MODE 2: out0[n]=acc+b                                         (layer 2, 128)
// ---------------------------------------------------------------------------
template <int MODE>
__global__ __launch_bounds__(256) void gather128_kernel(
    const float* __restrict__ H, const float2* __restrict__ edges,
    const int* __restrict__ indptr, const int* __restrict__ deg,
    const float* __restrict__ bias, const float* __restrict__ Bres,
    float* __restrict__ out0, float* __restrict__ out1)
{
    int warp = (blockIdx.x * 256 + threadIdx.x) >> 5;
    int lane = threadIdx.x & 31;
    if (warp >= N_NODES) return;
    int node = warp;

    int start = __ldg(&indptr[node]);
    int cnt   = __ldg(&deg[node]);

    float4 acc = make_float4(0.f, 0.f, 0.f, 0.f);
    const float4* H4 = (const float4*)H;

    int j = 0;
    for (; j + 1 < cnt; j += 2) {
        float2 e0 = __ldg(&edges[start + j]);
        float2 e1 = __ldg(&edges[start + j + 1]);
        float4 v0 = __ldg(&H4[(__float_as_int(e0.x) << 5) + lane]);
        float4 v1 = __ldg(&H4[(__float_as_int(e1.x) << 5) + lane]);
        acc.x = fmaf(v0.x, e0.y, acc.x); acc.y = fmaf(v0.y, e0.y, acc.y);
        acc.z = fmaf(v0.z, e0.y, acc.z); acc.w = fmaf(v0.w, e0.y, acc.w);
        acc.x = fmaf(v1.x, e1.y, acc.x); acc.y = fmaf(v1.y, e1.y, acc.y);
        acc.z = fmaf(v1.z, e1.y, acc.z); acc.w = fmaf(v1.w, e1.y, acc.w);
    }
    if (j < cnt) {
        float2 e0 = __ldg(&edges[start + j]);
        float4 v0 = __ldg(&H4[(__float_as_int(e0.x) << 5) + lane]);
        acc.x = fmaf(v0.x, e0.y, acc.x); acc.y = fmaf(v0.y, e0.y, acc.y);
        acc.z = fmaf(v0.z, e0.y, acc.z); acc.w = fmaf(v0.w, e0.y, acc.w);
    }

    float4 bb = ((const float4*)bias)[lane];
    float4 val = make_float4(acc.x + bb.x, acc.y + bb.y,
                             acc.z + bb.z, acc.w + bb.w);
    int idx = (node << 5) + lane;

    if (MODE == 0) {
        ((float4*)out0)[idx] = val;
        float4 c;
        c.x = val.x + fmaxf(val.x, 0.f); c.y = val.y + fmaxf(val.y, 0.f);
        c.z = val.z + fmaxf(val.z, 0.f); c.w = val.w + fmaxf(val.w, 0.f);
        ((float4*)out1)[idx] = c;
    } else if (MODE == 1) {
        float4 b = __ldg(&((const float4*)Bres)[idx]);
        float4 c;
        c.x = b.x + fmaxf(val.x, 0.f); c.y = b.y + fmaxf(val.y, 0.f);
        c.z = b.z + fmaxf(val.z, 0.f); c.w = b.w + fmaxf(val.w, 0.f);
        ((float4*)out0)[idx] = c;
    } else {
        ((float4*)out0)[idx] = val;
    }
}

// D=64: half-warp per node (16 chunks of float4), 2 nodes per warp.
__global__ __launch_bounds__(256) void gather64_kernel(
    const float* __restrict__ H, const float2* __restrict__ edges,
    const int* __restrict__ indptr, const int* __restrict__ deg,
    const float* __restrict__ bias, float* __restrict__ out)
{
    int half = (blockIdx.x * 256 + threadIdx.x) >> 4;   // half-warp id
    int lane = threadIdx.x & 15;
    if (half >= N_NODES) return;
    int node = half;

    int start = __ldg(&indptr[node]);
    int cnt   = __ldg(&deg[node]);

    float4 acc = make_float4(0.f, 0.f, 0.f, 0.f);
    const float4* H4 = (const float4*)H;

    int j = 0;
    for (; j + 1 < cnt; j += 2) {
        float2 e0 = __ldg(&edges[start + j]);
        float2 e1 = __ldg(&edges[start + j + 1]);
        float4 v0 = __ldg(&H4[(__float_as_int(e0.x) << 4) + lane]);
        float4 v1 = __ldg(&H4[(__float_as_int(e1.x) << 4) + lane]);
        acc.x = fmaf(v0.x, e0.y, acc.x); acc.y = fmaf(v0.y, e0.y, acc.y);
        acc.z = fmaf(v0.z, e0.y, acc.z); acc.w = fmaf(v0.w, e0.y, acc.w);
        acc.x = fmaf(v1.x, e1.y, acc.x); acc.y = fmaf(v1.y, e1.y, acc.y);
        acc.z = fmaf(v1.z, e1.y, acc.z); acc.w = fmaf(v1.w, e1.y, acc.w);
    }
    if (j < cnt) {
        float2 e0 = __ldg(&edges[start + j]);
        float4 v0 = __ldg(&H4[(__float_as_int(e0.x) << 4) + lane]);
        acc.x = fmaf(v0.x, e0.y, acc.x); acc.y = fmaf(v0.y, e0.y, acc.y);
        acc.z = fmaf(v0.z, e0.y, acc.z); acc.w = fmaf(v0.w, e0.y, acc.w);
    }

    float4 bb = ((const float4*)bias)[lane];
    float4 val = make_float4(acc.x + bb.x, acc.y + bb.y,
                             acc.z + bb.z, acc.w + bb.w);
    ((float4*)out)[(node << 4) + lane] = val;
}

// ---------------------------------------------------------------------------

extern "C" void kernel_launch(void* const* d_in, const int* in_sizes, int n_in,
                              void* d_out, int out_size)
{
    const float* x  = (const float*)d_in[0];
    const int*   ei = (const int*)d_in[1];
    const float* ea = (const float*)d_in[2];
    const float* W1 = (const float*)d_in[3];
    const float* b1 = (const float*)d_in[4];
    const float* W2 = (const float*)d_in[5];
    const float* b2 = (const float*)d_in[6];
    const float* W3 = (const float*)d_in[7];
    const float* b3 = (const float*)d_in[8];
    float* out = (float*)d_out;

    const int N = N_NODES;
    const int E = N_EDGES;
    const int* src = ei;
    const int* dst = ei + E;

    float *A, *B, *C;
    int *deg, *indptr, *cursor;
    float2* edges;
    cudaGetSymbolAddress((void**)&A, g_bufA);
    cudaGetSymbolAddress((void**)&B, g_bufB);
    cudaGetSymbolAddress((void**)&C, g_bufC);
    cudaGetSymbolAddress((void**)&deg, g_deg);
    cudaGetSymbolAddress((void**)&indptr, g_indptr);
    cudaGetSymbolAddress((void**)&cursor, g_cursor);
    cudaGetSymbolAddress((void**)&edges, g_edges);

    const size_t SMEM128 = (size_t)(128 * 128 + 64 * 132) * 4;
    const size_t SMEM64  = (size_t)(128 * 64  + 64 * 132) * 4;
    cudaFuncSetAttribute(gemm_kernel<128>, cudaFuncAttributeMaxDynamicSharedMemorySize, (int)SMEM128);
    cudaFuncSetAttribute(gemm_kernel<64>,  cudaFuncAttributeMaxDynamicSharedMemorySize, (int)SMEM64);

    const int gemm_blocks = (N + 63) / 64;
    const int e_blocks    = (E + 255) / 256;
    const int g128_blocks = (N * 32 + 255) / 256;   // warp per node
    const int g64_blocks  = (N * 16 + 255) / 256;   // half-warp per node

    // --- CSR build (reused by all 3 layers) ---
    cudaMemsetAsync(deg, 0, N * sizeof(int));
    hist_kernel<<<e_blocks, 256>>>(dst, deg, E);
    scan_kernel<<<1, 1024>>>(deg, indptr, cursor);
    place_kernel<<<e_blocks, 256>>>(src, dst, ea, cursor, edges, E);

    // --- Layer 0: B = x1 = agg(x@W1)+b1 ; C = x1 + relu(x1) ---
    gemm_kernel<128><<<gemm_blocks, 256, SMEM128>>>(x, W1, A, N);
    gather128_kernel<0><<<g128_blocks, 256>>>(A, edges, indptr, deg, b1, nullptr, B, C);

    // --- Layer 1: C = x1 + relu(agg(C@W2)+b2) ---
    gemm_kernel<128><<<gemm_blocks, 256, SMEM128>>>(C, W2, A, N);
    gather128_kernel<1><<<g128_blocks, 256>>>(A, edges, indptr, deg, b2, B, C, nullptr);

    // --- Layer 2: out = agg(C@W3)+b3 ---
    gemm_kernel<64><<<gemm_blocks, 256, SMEM64>>>(C, W3, A, N);
    gather64_kernel<<<g64_blocks, 256>>>(A, edges, indptr, deg, b3, out);
}

// round 3
// speedup vs baseline: 1.2469x; 1.0226x over previous
#include <cuda_runtime.h>
#include <cuda_bf16.h>

// ---------------------------------------------------------------------------
// QGCN forward on GB300 — CSR gather + register-blocked SGEMM.
// ---------------------------------------------------------------------------

#define N_NODES 50000
#define N_EDGES 800000

__device__ float  g_bufA[N_NODES * 128];
__device__ float  g_bufB[N_NODES * 128];
__device__ float  g_bufC[N_NODES * 128];
__device__ int    g_deg[N_NODES];
__device__ int    g_indptr[N_NODES];
__device__ int    g_cursor[N_NODES];
__device__ float2 g_edges[N_EDGES];   // {src (bit-cast int), weight}

// ---------------------------------------------------------------------------
// GEMM: Y[N, BN] = X[N, 128] @ W[128, BN].   8x8 thread tile, KC=16 chunks,
// register-prefetch pipeline. THREADS = BM*BN/64.
// ---------------------------------------------------------------------------
template <int BM, int BN>
__global__ __launch_bounds__(BM * BN / 64, 4) void gemm_kernel(
    const float* __restrict__ X, const float* __restrict__ W,
    float* __restrict__ Y, int N)
{
    constexpr int THREADS = BM * BN / 64;
    constexpr int KC = 16;
    constexpr int NK = 128 / KC;
    constexpr int APAD = 4;
    constexpr int LA = BM * KC / 4 / THREADS;   // float4s of A per thread
    constexpr int LB = BN * KC / 4 / THREADS;   // float4s of B per thread

    __shared__ float As[KC][BM + APAD];   // transposed: As[k][row]
    __shared__ float Bs[KC][BN];          // Bs[k][col]

    const int tid = threadIdx.x;
    const int row_base = blockIdx.x * BM;

    const float4* X4 = (const float4*)X;
    const float4* W4 = (const float4*)W;

    float4 aReg[LA], bReg[LB];

    auto ldgA = [&](int ch) {
#pragma unroll
        for (int i = 0; i < LA; i++) {
            int idx = tid + i * THREADS;
            int r = idx >> 2;          // KC/4 = 4 float4 per row
            int c4 = idx & 3;
            int gr = row_base + r;
            aReg[i] = (gr < N) ? X4[gr * 32 + ch * (KC / 4) + c4]
                               : make_float4(0.f, 0.f, 0.f, 0.f);
        }
    };
    auto ldgB = [&](int ch) {
#pragma unroll
        for (int i = 0; i < LB; i++) {
            int idx = tid + i * THREADS;
            int kk = idx / (BN / 4);
            int cc = idx % (BN / 4);
            bReg[i] = W4[(ch * KC + kk) * (BN / 4) + cc];
        }
    };
    auto stsAB = [&]() {
#pragma unroll
        for (int i = 0; i < LA; i++) {
            int idx = tid + i * THREADS;
            int r = idx >> 2;
            int c4 = idx & 3;
            As[c4 * 4 + 0][r] = aReg[i].x;
            As[c4 * 4 + 1][r] = aReg[i].y;
            As[c4 * 4 + 2][r] = aReg[i].z;
            As[c4 * 4 + 3][r] = aReg[i].w;
        }
#pragma unroll
        for (int i = 0; i < LB; i++) {
            int idx = tid + i * THREADS;
            int kk = idx / (BN / 4);
            int cc = idx % (BN / 4);
            *(float4*)&Bs[kk][cc * 4] = bReg[i];
        }
    };

    constexpr int TX = BN / 8;
    const int col0 = (tid % TX) * 8;
    const int row0 = (tid / TX) * 8;

    float acc[8][8] = {};

    ldgA(0); ldgB(0);
    stsAB();
    __syncthreads();

#pragma unroll
    for (int ch = 0; ch < NK; ch++) {
        if (ch + 1 < NK) { ldgA(ch + 1); ldgB(ch + 1); }
#pragma unroll
        for (int k = 0; k < KC; k++) {
            float4 a0 = *(const float4*)&As[k][row0];
            float4 a1 = *(const float4*)&As[k][row0 + 4];
            float4 b0 = *(const float4*)&Bs[k][col0];
            float4 b1 = *(const float4*)&Bs[k][col0 + 4];
            float av[8] = {a0.x, a0.y, a0.z, a0.w, a1.x, a1.y, a1.z, a1.w};
            float bv[8] = {b0.x, b0.y, b0.z, b0.w, b1.x, b1.y, b1.z, b1.w};
#pragma unroll
            for (int r = 0; r < 8; r++)
#pragma unroll
                for (int c = 0; c < 8; c++)
                    acc[r][c] = fmaf(av[r], bv[c], acc[r][c]);
        }
        if (ch + 1 < NK) {
            __syncthreads();
            stsAB();
            __syncthreads();
        }
    }

#pragma unroll
    for (int r = 0; r < 8; r++) {
        int gr = row_base + row0 + r;
        if (gr < N) {
            float4* Yp = (float4*)&Y[gr * BN + col0];
            Yp[0] = make_float4(acc[r][0], acc[r][1], acc[r][2], acc[r][3]);
            Yp[1] = make_float4(acc[r][4], acc[r][5], acc[r][6], acc[r][7]);
        }
    }
}

// ---------------------------------------------------------------------------
// CSR build
// ---------------------------------------------------------------------------
__global__ __launch_bounds__(256) void hist_kernel(
    const int* __restrict__ dst, int* __restrict__ deg, int E)
{
    int e = blockIdx.x * blockDim.x + threadIdx.x;
    if (e < E) atomicAdd(&deg[__ldg(&dst[e])], 1);
}

__global__ __launch_bounds__(1024) void scan_kernel(
    const int* __restrict__ deg, int* __restrict__ indptr,
    int* __restrict__ cursor)
{
    __shared__ int sh[1024];
    const int CHUNK = (N_NODES + 1023) / 1024;
    int t = threadIdx.x;
    int begin = t * CHUNK;
    int end   = begin + CHUNK; if (end > N_NODES) end = N_NODES;

    int s = 0;
    for (int i = begin; i < end; i++) s += deg[i];
    sh[t] = s;
    __syncthreads();

    for (int off = 1; off < 1024; off <<= 1) {
        int v = sh[t];
        int a = (t >= off) ? sh[t - off] : 0;
        __syncthreads();
        sh[t] = v + a;
        __syncthreads();
    }

    int run = (t == 0) ? 0 : sh[t - 1];
    for (int i = begin; i < end; i++) {
        indptr[i] = run;
        cursor[i] = run;
        run += deg[i];
    }
}

__global__ __launch_bounds__(256) void place_kernel(
    const int* __restrict__ src, const int* __restrict__ dst,
    const float* __restrict__ ew, int* __restrict__ cursor,
    float2* __restrict__ edges, int E)
{
    int e = blockIdx.x * blockDim.x + threadIdx.x;
    if (e >= E) return;
    int d = __ldg(&dst[e]);
    int p = atomicAdd(&cursor[d], 1);
    edges[p] = make_float2(__int_as_float(__ldg(&src[e])), __ldg(&ew[e]));
}

// ---------------------------------------------------------------------------
// Gather-aggregate, D=128: one warp per dst node, lane = float4 chunk.
// MODE 0: val=acc+b; out0=val; out1=val+relu(val)    (layer 0)
// MODE 1: val=acc+b; out0=Bres+relu(val)             (layer 1)
// ---------------------------------------------------------------------------
template <int MODE>
__global__ __launch_bounds__(256) void gather128_kernel(
    const float* __restrict__ H, const float2* __restrict__ edges,
    const int* __restrict__ indptr, const int* __restrict__ deg,
    const float* __restrict__ bias, const float* __restrict__ Bres,
    float* __restrict__ out0, float* __restrict__ out1)
{
    int warp = (blockIdx.x * 256 + threadIdx.x) >> 5;
    int lane = threadIdx.x & 31;
    if (warp >= N_NODES) return;
    int node = warp;

    int start = __ldg(&indptr[node]);
    int cnt   = __ldg(&deg[node]);

    float4 acc = make_float4(0.f, 0.f, 0.f, 0.f);
    const float4* H4 = (const float4*)H;

    int j = 0;
    for (; j + 1 < cnt; j += 2) {
        float2 e0 = __ldg(&edges[start + j]);
        float2 e1 = __ldg(&edges[start + j + 1]);
        float4 v0 = __ldg(&H4[(__float_as_int(e0.x) << 5) + lane]);
        float4 v1 = __ldg(&H4[(__float_as_int(e1.x) << 5) + lane]);
        acc.x = fmaf(v0.x, e0.y, acc.x); acc.y = fmaf(v0.y, e0.y, acc.y);
        acc.z = fmaf(v0.z, e0.y, acc.z); acc.w = fmaf(v0.w, e0.y, acc.w);
        acc.x = fmaf(v1.x, e1.y, acc.x); acc.y = fmaf(v1.y, e1.y, acc.y);
        acc.z = fmaf(v1.z, e1.y, acc.z); acc.w = fmaf(v1.w, e1.y, acc.w);
    }
    if (j < cnt) {
        float2 e0 = __ldg(&edges[start + j]);
        float4 v0 = __ldg(&H4[(__float_as_int(e0.x) << 5) + lane]);
        acc.x = fmaf(v0.x, e0.y, acc.x); acc.y = fmaf(v0.y, e0.y, acc.y);
        acc.z = fmaf(v0.z, e0.y, acc.z); acc.w = fmaf(v0.w, e0.y, acc.w);
    }

    float4 bb = ((const float4*)bias)[lane];
    float4 val = make_float4(acc.x + bb.x, acc.y + bb.y,
                             acc.z + bb.z, acc.w + bb.w);
    int idx = (node << 5) + lane;

    if (MODE == 0) {
        ((float4*)out0)[idx] = val;
        float4 c;
        c.x = val.x + fmaxf(val.x, 0.f); c.y = val.y + fmaxf(val.y, 0.f);
        c.z = val.z + fmaxf(val.z, 0.f); c.w = val.w + fmaxf(val.w, 0.f);
        ((float4*)out1)[idx] = c;
    } else {
        float4 b = __ldg(&((const float4*)Bres)[idx]);
        float4 c;
        c.x = b.x + fmaxf(val.x, 0.f); c.y = b.y + fmaxf(val.y, 0.f);
        c.z = b.z + fmaxf(val.z, 0.f); c.w = b.w + fmaxf(val.w, 0.f);
        ((float4*)out0)[idx] = c;
    }
}

// D=64: half-warp per node.
__global__ __launch_bounds__(256) void gather64_kernel(
    const float* __restrict__ H, const float2* __restrict__ edges,
    const int* __restrict__ indptr, const int* __restrict__ deg,
    const float* __restrict__ bias, float* __restrict__ out)
{
    int half = (blockIdx.x * 256 + threadIdx.x) >> 4;
    int lane = threadIdx.x & 15;
    if (half >= N_NODES) return;
    int node = half;

    int start = __ldg(&indptr[node]);
    int cnt   = __ldg(&deg[node]);

    float4 acc = make_float4(0.f, 0.f, 0.f, 0.f);
    const float4* H4 = (const float4*)H;

    int j = 0;
    for (; j + 1 < cnt; j += 2) {
        float2 e0 = __ldg(&edges[start + j]);
        float2 e1 = __ldg(&edges[start + j + 1]);
        float4 v0 = __ldg(&H4[(__float_as_int(e0.x) << 4) + lane]);
        float4 v1 = __ldg(&H4[(__float_as_int(e1.x) << 4) + lane]);
        acc.x = fmaf(v0.x, e0.y, acc.x); acc.y = fmaf(v0.y, e0.y, acc.y);
        acc.z = fmaf(v0.z, e0.y, acc.z); acc.w = fmaf(v0.w, e0.y, acc.w);
        acc.x = fmaf(v1.x, e1.y, acc.x); acc.y = fmaf(v1.y, e1.y, acc.y);
        acc.z = fmaf(v1.z, e1.y, acc.z); acc.w = fmaf(v1.w, e1.y, acc.w);
    }
    if (j < cnt) {
        float2 e0 = __ldg(&edges[start + j]);
        float4 v0 = __ldg(&H4[(__float_as_int(e0.x) << 4) + lane]);
        acc.x = fmaf(v0.x, e0.y, acc.x); acc.y = fmaf(v0.y, e0.y, acc.y);
        acc.z = fmaf(v0.z, e0.y, acc.z); acc.w = fmaf(v0.w, e0.y, acc.w);
    }

    float4 bb = ((const float4*)bias)[lane];
    ((float4*)out)[(node << 4) + lane] =
        make_float4(acc.x + bb.x, acc.y + bb.y, acc.z + bb.z, acc.w + bb.w);
}

// ---------------------------------------------------------------------------

extern "C" void kernel_launch(void* const* d_in, const int* in_sizes, int n_in,
                              void* d_out, int out_size)
{
    const float* x  = (const float*)d_in[0];
    const int*   ei = (const int*)d_in[1];
    const float* ea = (const float*)d_in[2];
    const float* W1 = (const float*)d_in[3];
    const float* b1 = (const float*)d_in[4];
    const float* W2 = (const float*)d_in[5];
    const float* b2 = (const float*)d_in[6];
    const float* W3 = (const float*)d_in[7];
    const float* b3 = (const float*)d_in[8];
    float* out = (float*)d_out;

    const int N = N_NODES;
    const int E = N_EDGES;
    const int* src = ei;
    const int* dst = ei + E;

    float *A, *B, *C;
    int *deg, *indptr, *cursor;
    float2* edges;
    cudaGetSymbolAddress((void**)&A, g_bufA);
    cudaGetSymbolAddress((void**)&B, g_bufB);
    cudaGetSymbolAddress((void**)&C, g_bufC);
    cudaGetSymbolAddress((void**)&deg, g_deg);
    cudaGetSymbolAddress((void**)&indptr, g_indptr);
    cudaGetSymbolAddress((void**)&cursor, g_cursor);
    cudaGetSymbolAddress((void**)&edges, g_edges);

    const int e_blocks    = (E + 255) / 256;
    const int g128_blocks = (N * 32 + 255) / 256;
    const int g64_blocks  = (N * 16 + 255) / 256;
    const int gemm128_blk = (N + 63) / 64;     // BM=64
    const int gemm64_blk  = (N + 127) / 128;   // BM=128

    // --- CSR build (reused by all 3 layers) ---
    cudaMemsetAsync(deg, 0, N * sizeof(int));
    hist_kernel<<<e_blocks, 256>>>(dst, deg, E);
    scan_kernel<<<1, 1024>>>(deg, indptr, cursor);
    place_kernel<<<e_blocks, 256>>>(src, dst, ea, cursor, edges, E);

    // --- Layer 0: B = x1 = agg(x@W1)+b1 ; C = x1 + relu(x1) ---
    gemm_kernel<64, 128><<<gemm128_blk, 128>>>(x, W1, A, N);
    gather128_kernel<0><<<g128_blocks, 256>>>(A, edges, indptr, deg, b1, nullptr, B, C);

    // --- Layer 1: C = x1 + relu(agg(C@W2)+b2) ---
    gemm_kernel<64, 128><<<gemm128_blk, 128>>>(C, W2, A, N);
    gather128_kernel<1><<<g128_blocks, 256>>>(A, edges, indptr, deg, b2, B, C, nullptr);

    // --- Layer 2: out = agg(C@W3)+b3 ---
    gemm_kernel<128, 64><<<gemm64_blk, 128>>>(C, W3, A, N);
    gather64_kernel<<<g64_blocks, 256>>>(A, edges, indptr, deg, b3, out);
}

// round 4
// speedup vs baseline: 1.8443x; 1.4791x over previous
#include <cuda_runtime.h>
#include <cuda_bf16.h>
#include <cstdint>

// ---------------------------------------------------------------------------
// QGCN forward on GB300 — CSR gather + split-TF32 tensor-core GEMM.
//   GEMM: Y = X @ W via mma.sync.m16n8k8.tf32, 3-pass hi/lo split (~fp32 acc).
// ---------------------------------------------------------------------------

#define N_NODES 50000
#define N_EDGES 800000

__device__ float  g_bufA[N_NODES * 128];
__device__ float  g_bufB[N_NODES * 128];
__device__ float  g_bufC[N_NODES * 128];
__device__ int    g_deg[N_NODES];
__device__ int    g_indptr[N_NODES];
__device__ int    g_cursor[N_NODES];
__device__ float2 g_edges[N_EDGES];   // {src (bit-cast int), weight}

// ---------------------------------------------------------------------------
// TF32 helpers
// ---------------------------------------------------------------------------
__device__ __forceinline__ uint32_t f2tf32(float x) {
    uint32_t r;
    asm("cvt.rna.tf32.f32 %0, %1;" : "=r"(r) : "f"(x));
    return r;
}
__device__ __forceinline__ void tf32_split(float x, uint32_t& hi, uint32_t& lo) {
    hi = f2tf32(x);
    lo = f2tf32(x - __uint_as_float(hi));
}
__device__ __forceinline__ void mma_tf32(
    float& d0, float& d1, float& d2, float& d3,
    uint32_t a0, uint32_t a1, uint32_t a2, uint32_t a3,
    uint32_t b0, uint32_t b1)
{
    asm volatile(
        "mma.sync.aligned.m16n8k8.row.col.f32.tf32.tf32.f32 "
        "{%0,%1,%2,%3},{%4,%5,%6,%7},{%8,%9},{%0,%1,%2,%3};"
        : "+f"(d0), "+f"(d1), "+f"(d2), "+f"(d3)
        : "r"(a0), "r"(a1), "r"(a2), "r"(a3), "r"(b0), "r"(b1));
}

// ---------------------------------------------------------------------------
// GEMM: Y[N, BNT] = X[N, 128] @ W[128, BNT]   (BNT = 128 or 64)
// Block tile 64x64, 128 threads (4 warps, warp tile 32x32), KC=32 chunks.
// ---------------------------------------------------------------------------
template <int BNT>
__global__ __launch_bounds__(128, 3) void gemm_tc_kernel(
    const float* __restrict__ X, const float* __restrict__ W,
    float* __restrict__ Y, int N)
{
    constexpr int KC  = 32;
    constexpr int NK  = 128 / KC;       // 4 chunks
    constexpr int XSP = 36;             // Xs row stride (conflict-free frags)
    constexpr int WSP = 72;             // Ws row stride (conflict-free frags)

    __shared__ float Xs[64][XSP];
    __shared__ float Ws[KC][WSP];

    const int tid  = threadIdx.x;
    const int lane = tid & 31;
    const int warp = tid >> 5;
    const int row0 = blockIdx.x * 64;
    const int nb   = blockIdx.y * 64;

    const int qr = lane >> 2;   // 0..7
    const int qt = lane & 3;    // 0..3
    const int wm = (warp & 1) * 32;
    const int wn = (warp >> 1) * 32;

    const float4* X4 = (const float4*)X;
    const float4* W4 = (const float4*)W;

    float4 xr[4], wr[4];

    auto ldgX = [&](int ch) {
#pragma unroll
        for (int i = 0; i < 4; i++) {
            int idx = tid + i * 128;            // over 64*8 float4
            int r = idx >> 3, c4 = idx & 7;
            int gr = row0 + r;
            xr[i] = (gr < N) ? X4[gr * 32 + ch * 8 + c4]
                             : make_float4(0.f, 0.f, 0.f, 0.f);
        }
    };
    auto ldgW = [&](int ch) {
#pragma unroll
        for (int i = 0; i < 4; i++) {
            int idx = tid + i * 128;            // over 32*16 float4
            int kk = idx >> 4, cc = idx & 15;
            wr[i] = W4[(((ch * KC + kk) * BNT + nb) >> 2) + cc];
        }
    };
    auto stsX = [&]() {
#pragma unroll
        for (int i = 0; i < 4; i++) {
            int idx = tid + i * 128;
            int r = idx >> 3, c4 = idx & 7;
            *(float4*)&Xs[r][c4 * 4] = xr[i];
        }
    };
    auto stsW = [&]() {
#pragma unroll
        for (int i = 0; i < 4; i++) {
            int idx = tid + i * 128;
            int kk = idx >> 4, cc = idx & 15;
            *(float4*)&Ws[kk][cc * 4] = wr[i];
        }
    };

    float acc[2][4][4] = {};

    ldgX(0); ldgW(0);
    stsX(); stsW();
    __syncthreads();

#pragma unroll
    for (int ch = 0; ch < NK; ch++) {
        if (ch + 1 < NK) { ldgX(ch + 1); ldgW(ch + 1); }

#pragma unroll
        for (int ks = 0; ks < KC / 8; ks++) {
            const int kb = ks * 8 + qt;

            // A fragments (2 m16 tiles), split hi/lo
            uint32_t ahi[2][4], alo[2][4];
#pragma unroll
            for (int mt = 0; mt < 2; mt++) {
                int r = wm + mt * 16 + qr;
                tf32_split(Xs[r][kb],         ahi[mt][0], alo[mt][0]);
                tf32_split(Xs[r + 8][kb],     ahi[mt][1], alo[mt][1]);
                tf32_split(Xs[r][kb + 4],     ahi[mt][2], alo[mt][2]);
                tf32_split(Xs[r + 8][kb + 4], ahi[mt][3], alo[mt][3]);
            }
            // B fragments (4 n8 tiles), split hi/lo
            uint32_t bhi[4][2], blo[4][2];
#pragma unroll
            for (int nt = 0; nt < 4; nt++) {
                int c = wn + nt * 8 + qr;
                tf32_split(Ws[ks * 8 + qt][c],     bhi[nt][0], blo[nt][0]);
                tf32_split(Ws[ks * 8 + qt + 4][c], bhi[nt][1], blo[nt][1]);
            }
#pragma unroll
            for (int mt = 0; mt < 2; mt++)
#pragma unroll
                for (int nt = 0; nt < 4; nt++) {
                    float* d = acc[mt][nt];
                    mma_tf32(d[0], d[1], d[2], d[3],
                             ahi[mt][0], ahi[mt][1], ahi[mt][2], ahi[mt][3],
                             bhi[nt][0], bhi[nt][1]);
                    mma_tf32(d[0], d[1], d[2], d[3],
                             ahi[mt][0], ahi[mt][1], ahi[mt][2], ahi[mt][3],
                             blo[nt][0], blo[nt][1]);
                    mma_tf32(d[0], d[1], d[2], d[3],
                             alo[mt][0], alo[mt][1], alo[mt][2], alo[mt][3],
                             bhi[nt][0], bhi[nt][1]);
                }
        }

        if (ch + 1 < NK) {
            __syncthreads();
            stsX(); stsW();
            __syncthreads();
        }
    }

    // Epilogue
#pragma unroll
    for (int mt = 0; mt < 2; mt++) {
#pragma unroll
        for (int nt = 0; nt < 4; nt++) {
            int gc = nb + wn + nt * 8 + qt * 2;
            int r0g = row0 + wm + mt * 16 + qr;
            if (r0g < N)
                *(float2*)&Y[r0g * BNT + gc] =
                    make_float2(acc[mt][nt][0], acc[mt][nt][1]);
            int r1g = r0g + 8;
            if (r1g < N)
                *(float2*)&Y[r1g * BNT + gc] =
                    make_float2(acc[mt][nt][2], acc[mt][nt][3]);
        }
    }
}

// ---------------------------------------------------------------------------
// CSR build
// ---------------------------------------------------------------------------
__global__ __launch_bounds__(256) void hist_kernel(
    const int* __restrict__ dst, int* __restrict__ deg, int E)
{
    int e = blockIdx.x * blockDim.x + threadIdx.x;
    if (e < E) atomicAdd(&deg[__ldg(&dst[e])], 1);
}

__global__ __launch_bounds__(1024) void scan_kernel(
    const int* __restrict__ deg, int* __restrict__ indptr,
    int* __restrict__ cursor)
{
    __shared__ int sh[1024];
    const int CHUNK = (N_NODES + 1023) / 1024;
    int t = threadIdx.x;
    int begin = t * CHUNK;
    int end   = begin + CHUNK; if (end > N_NODES) end = N_NODES;

    int s = 0;
    for (int i = begin; i < end; i++) s += deg[i];
    sh[t] = s;
    __syncthreads();

    for (int off = 1; off < 1024; off <<= 1) {
        int v = sh[t];
        int a = (t >= off) ? sh[t - off] : 0;
        __syncthreads();
        sh[t] = v + a;
        __syncthreads();
    }

    int run = (t == 0) ? 0 : sh[t - 1];
    for (int i = begin; i < end; i++) {
        indptr[i] = run;
        cursor[i] = run;
        run += deg[i];
    }
}

__global__ __launch_bounds__(256) void place_kernel(
    const int* __restrict__ src, const int* __restrict__ dst,
    const float* __restrict__ ew, int* __restrict__ cursor,
    float2* __restrict__ edges, int E)
{
    int e = blockIdx.x * blockDim.x + threadIdx.x;
    if (e >= E) return;
    int d = __ldg(&dst[e]);
    int p = atomicAdd(&cursor[d], 1);
    edges[p] = make_float2(__int_as_float(__ldg(&src[e])), __ldg(&ew[e]));
}

// ---------------------------------------------------------------------------
// Gather-aggregate, D=128: one warp per dst node, lane = float4 chunk.
// MODE 0: val=acc+b; out0=val; out1=val+relu(val)    (layer 0)
// MODE 1: val=acc+b; out0=Bres+relu(val)             (layer 1)
// ---------------------------------------------------------------------------
template <int MODE>
__global__ __launch_bounds__(256) void gather128_kernel(
    const float* __restrict__ H, const float2* __restrict__ edges,
    const int* __restrict__ indptr, const int* __restrict__ deg,
    const float* __restrict__ bias, const float* __restrict__ Bres,
    float* __restrict__ out0, float* __restrict__ out1)
{
    int warp = (blockIdx.x * 256 + threadIdx.x) >> 5;
    int lane = threadIdx.x & 31;
    if (warp >= N_NODES) return;
    int node = warp;

    int start = __ldg(&indptr[node]);
    int cnt   = __ldg(&deg[node]);

    float4 acc = make_float4(0.f, 0.f, 0.f, 0.f);
    const float4* H4 = (const float4*)H;

    int j = 0;
    for (; j + 1 < cnt; j += 2) {
        float2 e0 = __ldg(&edges[start + j]);
        float2 e1 = __ldg(&edges[start + j + 1]);
        float4 v0 = __ldg(&H4[(__float_as_int(e0.x) << 5) + lane]);
        float4 v1 = __ldg(&H4[(__float_as_int(e1.x) << 5) + lane]);
        acc.x = fmaf(v0.x, e0.y, acc.x); acc.y = fmaf(v0.y, e0.y, acc.y);
        acc.z = fmaf(v0.z, e0.y, acc.z); acc.w = fmaf(v0.w, e0.y, acc.w);
        acc.x = fmaf(v1.x, e1.y, acc.x); acc.y = fmaf(v1.y, e1.y, acc.y);
        acc.z = fmaf(v1.z, e1.y, acc.z); acc.w = fmaf(v1.w, e1.y, acc.w);
    }
    if (j < cnt) {
        float2 e0 = __ldg(&edges[start + j]);
        float4 v0 = __ldg(&H4[(__float_as_int(e0.x) << 5) + lane]);
        acc.x = fmaf(v0.x, e0.y, acc.x); acc.y = fmaf(v0.y, e0.y, acc.y);
        acc.z = fmaf(v0.z, e0.y, acc.z); acc.w = fmaf(v0.w, e0.y, acc.w);
    }

    float4 bb = ((const float4*)bias)[lane];
    float4 val = make_float4(acc.x + bb.x, acc.y + bb.y,
                             acc.z + bb.z, acc.w + bb.w);
    int idx = (node << 5) + lane;

    if (MODE == 0) {
        ((float4*)out0)[idx] = val;
        float4 c;
        c.x = val.x + fmaxf(val.x, 0.f); c.y = val.y + fmaxf(val.y, 0.f);
        c.z = val.z + fmaxf(val.z, 0.f); c.w = val.w + fmaxf(val.w, 0.f);
        ((float4*)out1)[idx] = c;
    } else {
        float4 b = __ldg(&((const float4*)Bres)[idx]);
        float4 c;
        c.x = b.x + fmaxf(val.x, 0.f); c.y = b.y + fmaxf(val.y, 0.f);
        c.z = b.z + fmaxf(val.z, 0.f); c.w = b.w + fmaxf(val.w, 0.f);
        ((float4*)out0)[idx] = c;
    }
}

// D=64: half-warp per node.
__global__ __launch_bounds__(256) void gather64_kernel(
    const float* __restrict__ H, const float2* __restrict__ edges,
    const int* __restrict__ indptr, const int* __restrict__ deg,
    const float* __restrict__ bias, float* __restrict__ out)
{
    int half = (blockIdx.x * 256 + threadIdx.x) >> 4;
    int lane = threadIdx.x & 15;
    if (half >= N_NODES) return;
    int node = half;

    int start = __ldg(&indptr[node]);
    int cnt   = __ldg(&deg[node]);

    float4 acc = make_float4(0.f, 0.f, 0.f, 0.f);
    const float4* H4 = (const float4*)H;

    int j = 0;
    for (; j + 1 < cnt; j += 2) {
        float2 e0 = __ldg(&edges[start + j]);
        float2 e1 = __ldg(&edges[start + j + 1]);
        float4 v0 = __ldg(&H4[(__float_as_int(e0.x) << 4) + lane]);
        float4 v1 = __ldg(&H4[(__float_as_int(e1.x) << 4) + lane]);
        acc.x = fmaf(v0.x, e0.y, acc.x); acc.y = fmaf(v0.y, e0.y, acc.y);
        acc.z = fmaf(v0.z, e0.y, acc.z); acc.w = fmaf(v0.w, e0.y, acc.w);
        acc.x = fmaf(v1.x, e1.y, acc.x); acc.y = fmaf(v1.y, e1.y, acc.y);
        acc.z = fmaf(v1.z, e1.y, acc.z); acc.w = fmaf(v1.w, e1.y, acc.w);
    }
    if (j < cnt) {
        float2 e0 = __ldg(&edges[start + j]);
        float4 v0 = __ldg(&H4[(__float_as_int(e0.x) << 4) + lane]);
        acc.x = fmaf(v0.x, e0.y, acc.x); acc.y = fmaf(v0.y, e0.y, acc.y);
        acc.z = fmaf(v0.z, e0.y, acc.z); acc.w = fmaf(v0.w, e0.y, acc.w);
    }

    float4 bb = ((const float4*)bias)[lane];
    ((float4*)out)[(node << 4) + lane] =
        make_float4(acc.x + bb.x, acc.y + bb.y, acc.z + bb.z, acc.w + bb.w);
}

// ---------------------------------------------------------------------------

extern "C" void kernel_launch(void* const* d_in, const int* in_sizes, int n_in,
                              void* d_out, int out_size)
{
    const float* x  = (const float*)d_in[0];
    const int*   ei = (const int*)d_in[1];
    const float* ea = (const float*)d_in[2];
    const float* W1 = (const float*)d_in[3];
    const float* b1 = (const float*)d_in[4];
    const float* W2 = (const float*)d_in[5];
    const float* b2 = (const float*)d_in[6];
    const float* W3 = (const float*)d_in[7];
    const float* b3 = (const float*)d_in[8];
    float* out = (float*)d_out;

    const int N = N_NODES;
    const int E = N_EDGES;
    const int* src = ei;
    const int* dst = ei + E;

    float *A, *B, *C;
    int *deg, *indptr, *cursor;
    float2* edges;
    cudaGetSymbolAddress((void**)&A, g_bufA);
    cudaGetSymbolAddress((void**)&B, g_bufB);
    cudaGetSymbolAddress((void**)&C, g_bufC);
    cudaGetSymbolAddress((void**)&deg, g_deg);
    cudaGetSymbolAddress((void**)&indptr, g_indptr);
    cudaGetSymbolAddress((void**)&cursor, g_cursor);
    cudaGetSymbolAddress((void**)&edges, g_edges);

    const int e_blocks    = (E + 255) / 256;
    const int g128_blocks = (N * 32 + 255) / 256;
    const int g64_blocks  = (N * 16 + 255) / 256;
    const int mrows       = (N + 63) / 64;          // 782

    dim3 grid128(mrows, 2);   // BNT=128
    dim3 grid64(mrows, 1);    // BNT=64

    // --- CSR build (reused by all 3 layers) ---
    cudaMemsetAsync(deg, 0, N * sizeof(int));
    hist_kernel<<<e_blocks, 256>>>(dst, deg, E);
    scan_kernel<<<1, 1024>>>(deg, indptr, cursor);
    place_kernel<<<e_blocks, 256>>>(src, dst, ea, cursor, edges, E);

    // --- Layer 0: B = x1 = agg(x@W1)+b1 ; C = x1 + relu(x1) ---
    gemm_tc_kernel<128><<<grid128, 128>>>(x, W1, A, N);
    gather128_kernel<0><<<g128_blocks, 256>>>(A, edges, indptr, deg, b1, nullptr, B, C);

    // --- Layer 1: C = x1 + relu(agg(C@W2)+b2) ---
    gemm_tc_kernel<128><<<grid128, 128>>>(C, W2, A, N);
    gather128_kernel<1><<<g128_blocks, 256>>>(A, edges, indptr, deg, b2, B, C, nullptr);

    // --- Layer 2: out = agg(C@W3)+b3 ---
    gemm_tc_kernel<64><<<grid64, 128>>>(C, W3, A, N);
    gather64_kernel<<<g64_blocks, 256>>>(A, edges, indptr, deg, b3, out);
}